// round 11
// baseline (speedup 1.0000x reference)
#include <cuda_runtime.h>
#include <cuda_bf16.h>
#include <cstdint>

// Problem constants
#define B_  2
#define S_  2048
#define D_  1024
#define H_  16
#define DK_ 64
#define M_  (B_ * S_)   // 4096
#define DSQ (D_ * D_)   // 1M

// ---------------------------------------------------------------------------
// Scratch: everything pre-split bf16 hi/lo.
// ---------------------------------------------------------------------------
__device__ __nv_bfloat16 g_Xh[3][M_ * D_];
__device__ __nv_bfloat16 g_Xl[3][M_ * D_];
__device__ __nv_bfloat16 g_Wh[4][DSQ];
__device__ __nv_bfloat16 g_Wl[4][DSQ];
__device__ __nv_bfloat16 g_Qh[M_ * D_];
__device__ __nv_bfloat16 g_Ql[M_ * D_];
__device__ __nv_bfloat16 g_Kh[M_ * D_];
__device__ __nv_bfloat16 g_Kl[M_ * D_];
__device__ __nv_bfloat16 g_Vh[M_ * D_];
__device__ __nv_bfloat16 g_Vl[M_ * D_];
__device__ __nv_bfloat16 g_Ch[M_ * D_];
__device__ __nv_bfloat16 g_Cl[M_ * D_];

__device__ __forceinline__ uint32_t smem_u32(const void* p) {
    uint32_t a;
    asm("{ .reg .u64 t; cvta.to.shared.u64 t, %1; cvt.u32.u64 %0, t; }"
        : "=r"(a) : "l"(p));
    return a;
}

__device__ __forceinline__ void mma16816(float* c,
                                         uint32_t a0, uint32_t a1, uint32_t a2, uint32_t a3,
                                         uint32_t b0, uint32_t b1) {
    asm volatile(
        "mma.sync.aligned.m16n8k16.row.col.f32.bf16.bf16.f32 "
        "{%0,%1,%2,%3}, {%4,%5,%6,%7}, {%8,%9}, {%0,%1,%2,%3};"
        : "+f"(c[0]), "+f"(c[1]), "+f"(c[2]), "+f"(c[3])
        : "r"(a0), "r"(a1), "r"(a2), "r"(a3), "r"(b0), "r"(b1));
}

__device__ __forceinline__ void ldsm4(uint32_t* r, uint32_t addr) {
    asm volatile("ldmatrix.sync.aligned.m8n8.x4.shared.b16 {%0,%1,%2,%3}, [%4];"
                 : "=r"(r[0]), "=r"(r[1]), "=r"(r[2]), "=r"(r[3]) : "r"(addr));
}

__device__ __forceinline__ void ldsm4t(uint32_t* r, uint32_t addr) {
    asm volatile("ldmatrix.sync.aligned.m8n8.x4.trans.shared.b16 {%0,%1,%2,%3}, [%4];"
                 : "=r"(r[0]), "=r"(r[1]), "=r"(r[2]), "=r"(r[3]) : "r"(addr));
}

#define CPASYNC16(saddr, gptr) \
    asm volatile("cp.async.cg.shared.global [%0], [%1], 16;" \
                 :: "r"((uint32_t)(saddr)), "l"(gptr))
#define CPCOMMIT() asm volatile("cp.async.commit_group;" ::: "memory")
#define CPWAIT1()  asm volatile("cp.async.wait_group 1;" ::: "memory")
#define CPWAIT0()  asm volatile("cp.async.wait_group 0;" ::: "memory")

__device__ __forceinline__ uint32_t packbf(float a, float b) {
    __nv_bfloat162 t = __floats2bfloat162_rn(a, b);
    return *(uint32_t*)&t;
}

// ===========================================================================
// Pre-split (batched over z): fp32 -> bf16 hi/lo
// ===========================================================================
__global__ __launch_bounds__(256) void presplit_kernel(
    const float* __restrict__ s0, const float* __restrict__ s1,
    const float* __restrict__ s2, const float* __restrict__ s3,
    __nv_bfloat16* __restrict__ dh, __nv_bfloat16* __restrict__ dl,
    size_t seg_elems, int n4)
{
    const int i = blockIdx.x * 256 + threadIdx.x;
    if (i >= n4) return;
    const int z = blockIdx.z;
    const float* src = (z == 0) ? s0 : (z == 1) ? s1 : (z == 2) ? s2 : s3;
    const size_t off = (size_t)z * seg_elems;
    float4 v = ((const float4*)src)[i];
    __nv_bfloat16 h0 = __float2bfloat16_rn(v.x);
    __nv_bfloat16 h1 = __float2bfloat16_rn(v.y);
    __nv_bfloat16 h2 = __float2bfloat16_rn(v.z);
    __nv_bfloat16 h3 = __float2bfloat16_rn(v.w);
    __nv_bfloat16 th[4] = { h0, h1, h2, h3 };
    __nv_bfloat16 tl[4] = {
        __float2bfloat16_rn(v.x - __bfloat162float(h0)),
        __float2bfloat16_rn(v.y - __bfloat162float(h1)),
        __float2bfloat16_rn(v.z - __bfloat162float(h2)),
        __float2bfloat16_rn(v.w - __bfloat162float(h3)) };
    ((uint64_t*)(dh + off))[i] = *(uint64_t*)th;
    ((uint64_t*)(dl + off))[i] = *(uint64_t*)tl;
}

// ===========================================================================
// Split-bf16 mma.sync GEMM+bias, cp.async double-buffered, pass-restructured.
// ===========================================================================
#define BM 128
#define BN 128
#define BK 32

#define GST 40960
#define GOFF_AH 0
#define GOFF_AL 10240
#define GOFF_BH 20480
#define GOFF_BL 30720
#define GEMM_SMEM_BYTES (2 * GST)   // 81920

template<int MODE>
__global__ __launch_bounds__(256, 2) void gemm_mma_kernel(
    const __nv_bfloat16* __restrict__ Ah0, const __nv_bfloat16* __restrict__ Al0,
    const float* __restrict__ bias0, const float* __restrict__ bias1, const float* __restrict__ bias2,
    float* __restrict__ Yf,
    __nv_bfloat16* __restrict__ Yh0, __nv_bfloat16* __restrict__ Yh1, __nv_bfloat16* __restrict__ Yh2,
    __nv_bfloat16* __restrict__ Yl0, __nv_bfloat16* __restrict__ Yl1, __nv_bfloat16* __restrict__ Yl2)
{
    extern __shared__ __align__(128) char smem[];
    const uint32_t sb = smem_u32(smem);

    const int tid  = threadIdx.x;
    const int lane = tid & 31;
    const int wid  = tid >> 5;
    const int wm   = wid >> 2;
    const int wn   = wid & 3;
    const int m0 = blockIdx.y * BM;
    const int n0 = blockIdx.x * BN;
    const int z  = blockIdx.z;

    const __nv_bfloat16* Ah;
    const __nv_bfloat16* Al;
    const __nv_bfloat16* Bh;
    const __nv_bfloat16* Bl;
    const float* bias;
    __nv_bfloat16* Yh;
    __nv_bfloat16* Yl;
    if (MODE == 0) {
        Ah = g_Xh[z]; Al = g_Xl[z];
        Bh = g_Wh[z]; Bl = g_Wl[z];
        bias = (z == 0) ? bias0 : (z == 1) ? bias1 : bias2;
        Yh = (z == 0) ? Yh0 : (z == 1) ? Yh1 : Yh2;
        Yl = (z == 0) ? Yl0 : (z == 1) ? Yl1 : Yl2;
    } else {
        Ah = Ah0; Al = Al0;
        Bh = g_Wh[3]; Bl = g_Wl[3];
        bias = bias0;
        Yh = nullptr; Yl = nullptr;
    }

    const uint32_t aoff = (uint32_t)((lane & 15) * 80 + (lane >> 4) * 16);
    const uint32_t boff = (uint32_t)(((lane & 7) + ((lane >> 4) & 1) * 8) * 80 +
                                     (((lane >> 3) & 1) ? 16 : 0));

    const int lrr = tid >> 2;
    const int lcc = tid & 3;

    float C[4][4][4];
#pragma unroll
    for (int i = 0; i < 4; i++)
#pragma unroll
        for (int j = 0; j < 4; j++)
#pragma unroll
            for (int t = 0; t < 4; t++) C[i][j][t] = 0.0f;

    auto issue_chunk = [&](int k0, uint32_t stage) {
#pragma unroll
        for (int i = 0; i < 2; i++) {
            const int r = lrr + i * 64;
            const size_t gA = (size_t)(m0 + r) * D_ + k0 + lcc * 8;
            const size_t gB = (size_t)(n0 + r) * D_ + k0 + lcc * 8;
            const uint32_t s = stage + (uint32_t)(r * 80 + lcc * 16);
            CPASYNC16(s + GOFF_AH, &Ah[gA]);
            CPASYNC16(s + GOFF_AL, &Al[gA]);
            CPASYNC16(s + GOFF_BH, &Bh[gB]);
            CPASYNC16(s + GOFF_BL, &Bl[gB]);
        }
        CPCOMMIT();
    };

    const int NCH = D_ / BK;
    issue_chunk(0, sb);

    for (int t = 0; t < NCH; t++) {
        if (t + 1 < NCH) {
            issue_chunk((t + 1) * BK, sb + ((t + 1) & 1) * GST);
            CPWAIT1();
        } else {
            CPWAIT0();
        }
        __syncthreads();

        const uint32_t st = sb + (t & 1) * GST;
        const uint32_t bAh = st + GOFF_AH;
        const uint32_t bAl = st + GOFF_AL;
        const uint32_t bBh = st + GOFF_BH;
        const uint32_t bBl = st + GOFF_BL;

#pragma unroll
        for (int ks = 0; ks < 2; ks++) {
            const uint32_t kbyte = (uint32_t)(ks * 32);
            uint32_t bh[2][4], bl[2][4];
#pragma unroll
            for (int p = 0; p < 2; p++) {
                ldsm4(bh[p], bBh + (uint32_t)((wn * 32 + p * 16) * 80) + kbyte + boff);
                ldsm4(bl[p], bBl + (uint32_t)((wn * 32 + p * 16) * 80) + kbyte + boff);
            }
#pragma unroll
            for (int ip = 0; ip < 2; ip++) {
                uint32_t ah[2][4], al[2][4];
#pragma unroll
                for (int i2 = 0; i2 < 2; i2++) {
                    ldsm4(ah[i2], bAh + (uint32_t)((wm * 64 + (ip * 2 + i2) * 16) * 80) + kbyte + aoff);
                    ldsm4(al[i2], bAl + (uint32_t)((wm * 64 + (ip * 2 + i2) * 16) * 80) + kbyte + aoff);
                }
#pragma unroll
                for (int i2 = 0; i2 < 2; i2++)
#pragma unroll
                    for (int j = 0; j < 4; j++)
                        mma16816(C[ip * 2 + i2][j], ah[i2][0], ah[i2][1], ah[i2][2], ah[i2][3],
                                 bh[j >> 1][(j & 1) * 2], bh[j >> 1][(j & 1) * 2 + 1]);
#pragma unroll
                for (int i2 = 0; i2 < 2; i2++)
#pragma unroll
                    for (int j = 0; j < 4; j++)
                        mma16816(C[ip * 2 + i2][j], ah[i2][0], ah[i2][1], ah[i2][2], ah[i2][3],
                                 bl[j >> 1][(j & 1) * 2], bl[j >> 1][(j & 1) * 2 + 1]);
#pragma unroll
                for (int i2 = 0; i2 < 2; i2++)
#pragma unroll
                    for (int j = 0; j < 4; j++)
                        mma16816(C[ip * 2 + i2][j], al[i2][0], al[i2][1], al[i2][2], al[i2][3],
                                 bh[j >> 1][(j & 1) * 2], bh[j >> 1][(j & 1) * 2 + 1]);
            }
        }
        __syncthreads();
    }

    const int qr = lane >> 2;
    const int qc = (lane & 3) * 2;
#pragma unroll
    for (int i = 0; i < 4; i++) {
        const int row0 = m0 + wm * 64 + i * 16 + qr;
#pragma unroll
        for (int j = 0; j < 4; j++) {
            const int col = n0 + wn * 32 + j * 8 + qc;
            const float b0v = bias[col], b1v = bias[col + 1];
            float v0 = C[i][j][0] + b0v, v1 = C[i][j][1] + b1v;
            float v2 = C[i][j][2] + b0v, v3 = C[i][j][3] + b1v;
            if (MODE == 0) {
                __nv_bfloat16 h0 = __float2bfloat16_rn(v0);
                __nv_bfloat16 h1 = __float2bfloat16_rn(v1);
                __nv_bfloat16 h2 = __float2bfloat16_rn(v2);
                __nv_bfloat16 h3 = __float2bfloat16_rn(v3);
                __nv_bfloat162 hp0; hp0.x = h0; hp0.y = h1;
                __nv_bfloat162 hp1; hp1.x = h2; hp1.y = h3;
                *(uint32_t*)&Yh[(size_t)row0 * D_ + col]       = *(uint32_t*)&hp0;
                *(uint32_t*)&Yh[(size_t)(row0 + 8) * D_ + col] = *(uint32_t*)&hp1;
                *(uint32_t*)&Yl[(size_t)row0 * D_ + col] =
                    packbf(v0 - __bfloat162float(h0), v1 - __bfloat162float(h1));
                *(uint32_t*)&Yl[(size_t)(row0 + 8) * D_ + col] =
                    packbf(v2 - __bfloat162float(h2), v3 - __bfloat162float(h3));
            } else {
                float2 o0 = { v0, v1 };
                float2 o1 = { v2, v3 };
                *(float2*)&Yf[(size_t)row0 * D_ + col]       = o0;
                *(float2*)&Yf[(size_t)(row0 + 8) * D_ + col] = o1;
            }
        }
    }
}

// ===========================================================================
// Flash attention: pass-restructured MMA issue, register-clamped to 128
// (launch_bounds min-blocks 2) with reduced live fragments (kh/vh preloaded,
// kl/vl streamed).
// ===========================================================================
#define ATQ 128
#define ATK 64
#define ALD 144

#define AOFF_QH 0
#define AOFF_QL (AOFF_QH + ATQ * ALD)
#define AOFF_BUF (AOFF_QL + ATQ * ALD)
#define BUF_BYTES (4 * ATK * ALD)
#define BKH 0
#define BKL (ATK * ALD)
#define BVH (2 * ATK * ALD)
#define BVL (3 * ATK * ALD)
#define ATTN_SMEM_BYTES (AOFF_BUF + 2 * BUF_BYTES)   // 110592

__global__ __launch_bounds__(256, 2) void attn_mma_kernel(
    const __nv_bfloat16* __restrict__ Qh, const __nv_bfloat16* __restrict__ Ql,
    const __nv_bfloat16* __restrict__ Kh, const __nv_bfloat16* __restrict__ Kl,
    const __nv_bfloat16* __restrict__ Vh, const __nv_bfloat16* __restrict__ Vl,
    const int* __restrict__ mask,
    __nv_bfloat16* __restrict__ Ch, __nv_bfloat16* __restrict__ Cl)
{
    extern __shared__ __align__(128) char smem[];
    const uint32_t sb = smem_u32(smem);

    const int tid  = threadIdx.x;
    const int lane = tid & 31;
    const int wid  = tid >> 5;
    const int bh = blockIdx.y;
    const int b  = bh >> 4;
    const int h  = bh & 15;
    const int q0 = blockIdx.x * ATQ;

    const size_t base = (size_t)b * S_ * D_ + (size_t)h * DK_;
    const __nv_bfloat16* Qhb = Qh + base;
    const __nv_bfloat16* Qlb = Ql + base;
    const __nv_bfloat16* Khb = Kh + base;
    const __nv_bfloat16* Klb = Kl + base;
    const __nv_bfloat16* Vhb = Vh + base;
    const __nv_bfloat16* Vlb = Vl + base;
    const int* Mb = mask + (size_t)b * S_ * S_;

    const int krr = tid >> 3;
    const int kcc = tid & 7;

    {
#pragma unroll
        for (int i = 0; i < 2; i++) {
            const int rr = krr + i * 32;
            const size_t g = (size_t)rr * D_ + kcc * 8;
            const uint32_t s = sb + AOFF_BUF + rr * ALD + kcc * 16;
            CPASYNC16(s + BKH, &Khb[g]);
            CPASYNC16(s + BKL, &Klb[g]);
            CPASYNC16(s + BVH, &Vhb[g]);
            CPASYNC16(s + BVL, &Vlb[g]);
        }
        CPCOMMIT();
#pragma unroll
        for (int i = 0; i < 4; i++) {
            const int idx = tid + i * 256;
            const int rr = idx >> 3;
            const int cc = idx & 7;
            *(uint4*)(smem + AOFF_QH + rr * ALD + cc * 16) =
                *(const uint4*)&Qhb[(size_t)(q0 + rr) * D_ + cc * 8];
            *(uint4*)(smem + AOFF_QL + rr * ALD + cc * 16) =
                *(const uint4*)&Qlb[(size_t)(q0 + rr) * D_ + cc * 8];
        }
    }

    const uint32_t aoffQ = sb + (uint32_t)((wid * 16 + (lane & 15)) * ALD + (lane >> 4) * 16);
    const uint32_t loffK = (uint32_t)(((lane & 7) + ((lane >> 4) & 1) * 8) * ALD +
                                      ((lane >> 3) & 1) * 16);
    const uint32_t loffV = (uint32_t)((((lane >> 3) & 1) * 8 + (lane & 7)) * ALD +
                                      ((lane >> 4) & 1) * 16);

    float mstate[2] = { -1e30f, -1e30f };
    float lstate[2] = { 0.0f, 0.0f };
    float O[8][4];
#pragma unroll
    for (int j = 0; j < 8; j++)
#pragma unroll
        for (int t = 0; t < 4; t++) O[j][t] = 0.0f;

    const int row0 = q0 + wid * 16 + (lane >> 2);
    const int mcol = (lane & 3) * 2;
    const int* mrow0 = Mb + (size_t)row0 * S_;
    const int* mrow1 = Mb + (size_t)(row0 + 8) * S_;

    const int NT = S_ / ATK;
    for (int t = 0; t < NT; t++) {
        const int k0 = t * ATK;
        if (t + 1 < NT) {
            const uint32_t nb = sb + AOFF_BUF + ((t + 1) & 1) * BUF_BYTES;
#pragma unroll
            for (int i = 0; i < 2; i++) {
                const int rr = krr + i * 32;
                const size_t g = (size_t)(k0 + ATK + rr) * D_ + kcc * 8;
                const uint32_t s = nb + rr * ALD + kcc * 16;
                CPASYNC16(s + BKH, &Khb[g]);
                CPASYNC16(s + BKL, &Klb[g]);
                CPASYNC16(s + BVH, &Vhb[g]);
                CPASYNC16(s + BVL, &Vlb[g]);
            }
            CPCOMMIT();
            CPWAIT1();
        } else {
            CPWAIT0();
        }
        __syncthreads();

        const uint32_t cb = sb + AOFF_BUF + (t & 1) * BUF_BYTES;
        const uint32_t boffK = cb + loffK;
        const uint32_t voffV = cb + loffV;

        // ---- S = Q K^T: kh preloaded (passes 1,3), kl streamed (pass 2) ----
        float Sf[8][4];
#pragma unroll
        for (int j = 0; j < 8; j++)
#pragma unroll
            for (int tt = 0; tt < 4; tt++) Sf[j][tt] = 0.0f;

#pragma unroll
        for (int kc = 0; kc < 4; kc++) {
            const uint32_t kb = (uint32_t)(kc * 32);
            uint32_t ah[4], al[4];
            ldsm4(ah, aoffQ + AOFF_QH + kb);
            ldsm4(al, aoffQ + AOFF_QL + kb);
            uint32_t kh[4][4];
#pragma unroll
            for (int jp = 0; jp < 4; jp++)
                ldsm4(kh[jp], boffK + BKH + (uint32_t)(jp * 16 * ALD) + kb);
            // pass 1: Qh*Kh
#pragma unroll
            for (int jp = 0; jp < 4; jp++) {
                mma16816(Sf[jp * 2],     ah[0], ah[1], ah[2], ah[3], kh[jp][0], kh[jp][1]);
                mma16816(Sf[jp * 2 + 1], ah[0], ah[1], ah[2], ah[3], kh[jp][2], kh[jp][3]);
            }
            // pass 2: Qh*Kl (kl streamed)
#pragma unroll
            for (int jp = 0; jp < 4; jp++) {
                uint32_t kl[4];
                ldsm4(kl, boffK + BKL + (uint32_t)(jp * 16 * ALD) + kb);
                mma16816(Sf[jp * 2],     ah[0], ah[1], ah[2], ah[3], kl[0], kl[1]);
                mma16816(Sf[jp * 2 + 1], ah[0], ah[1], ah[2], ah[3], kl[2], kl[3]);
            }
            // pass 3: Ql*Kh
#pragma unroll
            for (int jp = 0; jp < 4; jp++) {
                mma16816(Sf[jp * 2],     al[0], al[1], al[2], al[3], kh[jp][0], kh[jp][1]);
                mma16816(Sf[jp * 2 + 1], al[0], al[1], al[2], al[3], kh[jp][2], kh[jp][3]);
            }
        }

#pragma unroll
        for (int j = 0; j < 8; j++) {
            int2 mv0 = *(const int2*)&mrow0[k0 + j * 8 + mcol];
            int2 mv1 = *(const int2*)&mrow1[k0 + j * 8 + mcol];
            Sf[j][0] = (mv0.x == 0) ? -1e9f : Sf[j][0] * 0.125f;
            Sf[j][1] = (mv0.y == 0) ? -1e9f : Sf[j][1] * 0.125f;
            Sf[j][2] = (mv1.x == 0) ? -1e9f : Sf[j][2] * 0.125f;
            Sf[j][3] = (mv1.y == 0) ? -1e9f : Sf[j][3] * 0.125f;
        }

        float corr[2];
#pragma unroll
        for (int rr = 0; rr < 2; rr++) {
            float mx = -1e30f;
#pragma unroll
            for (int j = 0; j < 8; j++)
                mx = fmaxf(mx, fmaxf(Sf[j][rr * 2], Sf[j][rr * 2 + 1]));
            mx = fmaxf(mx, __shfl_xor_sync(0xFFFFFFFF, mx, 1));
            mx = fmaxf(mx, __shfl_xor_sync(0xFFFFFFFF, mx, 2));
            float mnew = fmaxf(mstate[rr], mx);
            corr[rr] = __expf(mstate[rr] - mnew);
            float sum = 0.0f;
#pragma unroll
            for (int j = 0; j < 8; j++) {
                float p0 = __expf(Sf[j][rr * 2]     - mnew);
                float p1 = __expf(Sf[j][rr * 2 + 1] - mnew);
                Sf[j][rr * 2] = p0; Sf[j][rr * 2 + 1] = p1;
                sum += p0 + p1;
            }
            sum += __shfl_xor_sync(0xFFFFFFFF, sum, 1);
            sum += __shfl_xor_sync(0xFFFFFFFF, sum, 2);
            lstate[rr] = lstate[rr] * corr[rr] + sum;
            mstate[rr] = mnew;
        }

#pragma unroll
        for (int j = 0; j < 8; j++) {
            O[j][0] *= corr[0]; O[j][1] *= corr[0];
            O[j][2] *= corr[1]; O[j][3] *= corr[1];
        }

        // ---- O += P V: vh preloaded (passes 1,3), vl streamed (pass 2) ----
#pragma unroll
        for (int kc = 0; kc < 4; kc++) {
            uint32_t Ph[4], Pl[4];
#pragma unroll
            for (int half = 0; half < 2; half++) {
                const int j = kc * 2 + half;
#pragma unroll
                for (int rr = 0; rr < 2; rr++) {
                    float p0 = Sf[j][rr * 2], p1 = Sf[j][rr * 2 + 1];
                    __nv_bfloat16 h0 = __float2bfloat16_rn(p0);
                    __nv_bfloat16 h1 = __float2bfloat16_rn(p1);
                    __nv_bfloat162 hp; hp.x = h0; hp.y = h1;
                    Ph[half * 2 + rr] = *(uint32_t*)&hp;
                    Pl[half * 2 + rr] =
                        packbf(p0 - __bfloat162float(h0), p1 - __bfloat162float(h1));
                }
            }
            uint32_t vh[4][4];
#pragma unroll
            for (int jp = 0; jp < 4; jp++)
                ldsm4t(vh[jp], voffV + BVH + (uint32_t)(kc * 16 * ALD) + (uint32_t)(jp * 32));
            // pass 1: Ph*Vh
#pragma unroll
            for (int jp = 0; jp < 4; jp++) {
                mma16816(O[jp * 2],     Ph[0], Ph[1], Ph[2], Ph[3], vh[jp][0], vh[jp][1]);
                mma16816(O[jp * 2 + 1], Ph[0], Ph[1], Ph[2], Ph[3], vh[jp][2], vh[jp][3]);
            }
            // pass 2: Ph*Vl (vl streamed)
#pragma unroll
            for (int jp = 0; jp < 4; jp++) {
                uint32_t vl[4];
                ldsm4t(vl, voffV + BVL + (uint32_t)(kc * 16 * ALD) + (uint32_t)(jp * 32));
                mma16816(O[jp * 2],     Ph[0], Ph[1], Ph[2], Ph[3], vl[0], vl[1]);
                mma16816(O[jp * 2 + 1], Ph[0], Ph[1], Ph[2], Ph[3], vl[2], vl[3]);
            }
            // pass 3: Pl*Vh
#pragma unroll
            for (int jp = 0; jp < 4; jp++) {
                mma16816(O[jp * 2],     Pl[0], Pl[1], Pl[2], Pl[3], vh[jp][0], vh[jp][1]);
                mma16816(O[jp * 2 + 1], Pl[0], Pl[1], Pl[2], Pl[3], vh[jp][2], vh[jp][3]);
            }
        }
        __syncthreads();
    }

    const float inv0 = 1.0f / lstate[0];
    const float inv1 = 1.0f / lstate[1];
    __nv_bfloat16* Chb = Ch + base;
    __nv_bfloat16* Clb = Cl + base;
#pragma unroll
    for (int j = 0; j < 8; j++) {
        const int col = j * 8 + mcol;
        float v0 = O[j][0] * inv0, v1 = O[j][1] * inv0;
        float v2 = O[j][2] * inv1, v3 = O[j][3] * inv1;
        __nv_bfloat16 h0 = __float2bfloat16_rn(v0);
        __nv_bfloat16 h1 = __float2bfloat16_rn(v1);
        __nv_bfloat16 h2 = __float2bfloat16_rn(v2);
        __nv_bfloat16 h3 = __float2bfloat16_rn(v3);
        __nv_bfloat162 hp0; hp0.x = h0; hp0.y = h1;
        __nv_bfloat162 hp1; hp1.x = h2; hp1.y = h3;
        *(uint32_t*)&Chb[(size_t)row0 * D_ + col]       = *(uint32_t*)&hp0;
        *(uint32_t*)&Chb[(size_t)(row0 + 8) * D_ + col] = *(uint32_t*)&hp1;
        *(uint32_t*)&Clb[(size_t)row0 * D_ + col] =
            packbf(v0 - __bfloat162float(h0), v1 - __bfloat162float(h1));
        *(uint32_t*)&Clb[(size_t)(row0 + 8) * D_ + col] =
            packbf(v2 - __bfloat162float(h2), v3 - __bfloat162float(h3));
    }
}

// ---------------------------------------------------------------------------
// Launch
// ---------------------------------------------------------------------------
extern "C" void kernel_launch(void* const* d_in, const int* in_sizes, int n_in,
                              void* d_out, int out_size)
{
    (void)in_sizes; (void)n_in; (void)out_size;
    const float* q    = (const float*)d_in[0];
    const float* k    = (const float*)d_in[1];
    const float* v    = (const float*)d_in[2];
    const int*   mask = (const int*)d_in[3];
    const float* w_q  = (const float*)d_in[4];
    const float* b_q  = (const float*)d_in[5];
    const float* w_k  = (const float*)d_in[6];
    const float* b_k  = (const float*)d_in[7];
    const float* w_v  = (const float*)d_in[8];
    const float* b_v  = (const float*)d_in[9];
    const float* w_o  = (const float*)d_in[10];
    const float* b_o  = (const float*)d_in[11];
    float* out = (float*)d_out;

    __nv_bfloat16 *gXh, *gXl, *gWh, *gWl;
    __nv_bfloat16 *gQh, *gQl, *gKh, *gKl, *gVh, *gVl, *gCh, *gCl;
    cudaGetSymbolAddress((void**)&gXh, g_Xh);
    cudaGetSymbolAddress((void**)&gXl, g_Xl);
    cudaGetSymbolAddress((void**)&gWh, g_Wh);
    cudaGetSymbolAddress((void**)&gWl, g_Wl);
    cudaGetSymbolAddress((void**)&gQh, g_Qh);
    cudaGetSymbolAddress((void**)&gQl, g_Ql);
    cudaGetSymbolAddress((void**)&gKh, g_Kh);
    cudaGetSymbolAddress((void**)&gKl, g_Kl);
    cudaGetSymbolAddress((void**)&gVh, g_Vh);
    cudaGetSymbolAddress((void**)&gVl, g_Vl);
    cudaGetSymbolAddress((void**)&gCh, g_Ch);
    cudaGetSymbolAddress((void**)&gCl, g_Cl);

    cudaFuncSetAttribute(attn_mma_kernel,
                         cudaFuncAttributeMaxDynamicSharedMemorySize,
                         ATTN_SMEM_BYTES);
    cudaFuncSetAttribute(gemm_mma_kernel<0>,
                         cudaFuncAttributeMaxDynamicSharedMemorySize,
                         GEMM_SMEM_BYTES);
    cudaFuncSetAttribute(gemm_mma_kernel<1>,
                         cudaFuncAttributeMaxDynamicSharedMemorySize,
                         GEMM_SMEM_BYTES);

    const int n4x = (M_ * D_) / 4;
    const int n4w = DSQ / 4;
    {
        dim3 g((n4x + 255) / 256, 1, 3);
        presplit_kernel<<<g, 256>>>(q, k, v, nullptr, gXh, gXl, (size_t)M_ * D_, n4x);
    }
    {
        dim3 g((n4w + 255) / 256, 1, 4);
        presplit_kernel<<<g, 256>>>(w_q, w_k, w_v, w_o, gWh, gWl, (size_t)DSQ, n4w);
    }

    dim3 gblk(256);
    dim3 ggrid3(D_ / BN, M_ / BM, 3);
    gemm_mma_kernel<0><<<ggrid3, gblk, GEMM_SMEM_BYTES>>>(
        nullptr, nullptr, b_q, b_k, b_v, nullptr,
        gQh, gKh, gVh, gQl, gKl, gVl);

    dim3 ablk(256);
    dim3 agrid(S_ / ATQ, B_ * H_);
    attn_mma_kernel<<<agrid, ablk, ATTN_SMEM_BYTES>>>(
        gQh, gQl, gKh, gKl, gVh, gVl, mask, gCh, gCl);

    dim3 ggrid1(D_ / BN, M_ / BM, 1);
    gemm_mma_kernel<1><<<ggrid1, gblk, GEMM_SMEM_BYTES>>>(
        gCh, gCl, b_o, nullptr, nullptr, out,
        nullptr, nullptr, nullptr, nullptr, nullptr, nullptr);
}

// round 12
// speedup vs baseline: 1.6070x; 1.6070x over previous
#include <cuda_runtime.h>
#include <cuda_bf16.h>
#include <cstdint>

// Problem constants
#define B_  2
#define S_  2048
#define D_  1024
#define H_  16
#define DK_ 64
#define M_  (B_ * S_)   // 4096

// ---------------------------------------------------------------------------
// Scratch: Q/K/V and context stored pre-split as bf16 hi/lo.
// ---------------------------------------------------------------------------
__device__ __nv_bfloat16 g_Qh[M_ * D_];
__device__ __nv_bfloat16 g_Ql[M_ * D_];
__device__ __nv_bfloat16 g_Kh[M_ * D_];
__device__ __nv_bfloat16 g_Kl[M_ * D_];
__device__ __nv_bfloat16 g_Vh[M_ * D_];
__device__ __nv_bfloat16 g_Vl[M_ * D_];
__device__ __nv_bfloat16 g_Ch[M_ * D_];
__device__ __nv_bfloat16 g_Cl[M_ * D_];

__device__ __forceinline__ uint32_t smem_u32(const void* p) {
    uint32_t a;
    asm("{ .reg .u64 t; cvta.to.shared.u64 t, %1; cvt.u32.u64 %0, t; }"
        : "=r"(a) : "l"(p));
    return a;
}

__device__ __forceinline__ void mma16816(float* c,
                                         uint32_t a0, uint32_t a1, uint32_t a2, uint32_t a3,
                                         uint32_t b0, uint32_t b1) {
    asm volatile(
        "mma.sync.aligned.m16n8k16.row.col.f32.bf16.bf16.f32 "
        "{%0,%1,%2,%3}, {%4,%5,%6,%7}, {%8,%9}, {%0,%1,%2,%3};"
        : "+f"(c[0]), "+f"(c[1]), "+f"(c[2]), "+f"(c[3])
        : "r"(a0), "r"(a1), "r"(a2), "r"(a3), "r"(b0), "r"(b1));
}

__device__ __forceinline__ void ldsm4(uint32_t* r, uint32_t addr) {
    asm volatile("ldmatrix.sync.aligned.m8n8.x4.shared.b16 {%0,%1,%2,%3}, [%4];"
                 : "=r"(r[0]), "=r"(r[1]), "=r"(r[2]), "=r"(r[3]) : "r"(addr));
}

__device__ __forceinline__ void ldsm4t(uint32_t* r, uint32_t addr) {
    asm volatile("ldmatrix.sync.aligned.m8n8.x4.trans.shared.b16 {%0,%1,%2,%3}, [%4];"
                 : "=r"(r[0]), "=r"(r[1]), "=r"(r[2]), "=r"(r[3]) : "r"(addr));
}

union PackB4 { uint64_t u; __nv_bfloat16 b[4]; };

__device__ __forceinline__ void split4(float4 v, uint64_t& hi, uint64_t& lo) {
    PackB4 h, l;
    h.b[0] = __float2bfloat16_rn(v.x);
    h.b[1] = __float2bfloat16_rn(v.y);
    h.b[2] = __float2bfloat16_rn(v.z);
    h.b[3] = __float2bfloat16_rn(v.w);
    l.b[0] = __float2bfloat16_rn(v.x - __bfloat162float(h.b[0]));
    l.b[1] = __float2bfloat16_rn(v.y - __bfloat162float(h.b[1]));
    l.b[2] = __float2bfloat16_rn(v.z - __bfloat162float(h.b[2]));
    l.b[3] = __float2bfloat16_rn(v.w - __bfloat162float(h.b[3]));
    hi = h.u; lo = l.u;
}

__device__ __forceinline__ uint32_t packbf(float a, float b) {
    __nv_bfloat162 t = __floats2bfloat162_rn(a, b);
    return *(uint32_t*)&t;
}

// ===========================================================================
// Split-bf16 mma.sync GEMM+bias (R7 version — best measured: 251us for z=3).
// MODE 0: fp32 X in, bf16 hi/lo out (Q/K/V projections; batched over z)
// MODE 1: pre-split bf16 A in (Ah/Al), fp32 out (final projection)
// ===========================================================================
#define BM 128
#define BN 128
#define BK 32

template<int MODE>
__global__ __launch_bounds__(256, 2) void gemm_mma_kernel(
    const float* __restrict__ X0, const float* __restrict__ X1, const float* __restrict__ X2,
    const __nv_bfloat16* __restrict__ Ah, const __nv_bfloat16* __restrict__ Al,
    const float* __restrict__ W0, const float* __restrict__ W1, const float* __restrict__ W2,
    const float* __restrict__ bias0, const float* __restrict__ bias1, const float* __restrict__ bias2,
    float* __restrict__ Yf,
    __nv_bfloat16* __restrict__ Yh0, __nv_bfloat16* __restrict__ Yh1, __nv_bfloat16* __restrict__ Yh2,
    __nv_bfloat16* __restrict__ Yl0, __nv_bfloat16* __restrict__ Yl1, __nv_bfloat16* __restrict__ Yl2)
{
    __shared__ __align__(128) __nv_bfloat16 sAh[BM * 40];
    __shared__ __align__(128) __nv_bfloat16 sAl[BM * 40];
    __shared__ __align__(128) __nv_bfloat16 sBh[BN * 40];
    __shared__ __align__(128) __nv_bfloat16 sBl[BN * 40];

    const int tid  = threadIdx.x;
    const int lane = tid & 31;
    const int wid  = tid >> 5;
    const int wm   = wid >> 2;
    const int wn   = wid & 3;
    const int m0 = blockIdx.y * BM;
    const int n0 = blockIdx.x * BN;
    const int z  = blockIdx.z;

    const float* X = (z == 0) ? X0 : (z == 1) ? X1 : X2;
    const float* W = (z == 0) ? W0 : (z == 1) ? W1 : W2;
    const float* bias = (z == 0) ? bias0 : (z == 1) ? bias1 : bias2;
    __nv_bfloat16* Yh = (z == 0) ? Yh0 : (z == 1) ? Yh1 : Yh2;
    __nv_bfloat16* Yl = (z == 0) ? Yl0 : (z == 1) ? Yl1 : Yl2;

    const uint32_t bAh = smem_u32(sAh);
    const uint32_t bAl = smem_u32(sAl);
    const uint32_t bBh = smem_u32(sBh);
    const uint32_t bBl = smem_u32(sBl);

    const uint32_t aoff = (uint32_t)((lane & 15) * 80 + (lane >> 4) * 16);
    const uint32_t boff = (uint32_t)(((lane & 7) + ((lane >> 4) & 1) * 8) * 80 +
                                     (((lane >> 3) & 1) ? 16 : 0));

    const int lr = tid >> 3;
    const int lc = tid & 7;

    float C[4][4][4];
#pragma unroll
    for (int i = 0; i < 4; i++)
#pragma unroll
        for (int j = 0; j < 4; j++)
#pragma unroll
            for (int t = 0; t < 4; t++) C[i][j][t] = 0.0f;

    for (int k0 = 0; k0 < D_; k0 += BK) {
        __syncthreads();
        if (MODE == 0) {
#pragma unroll
            for (int it = 0; it < 4; it++) {
                const int r = lr + it * 32;
                uint64_t hi, lo;
                float4 xv = *(const float4*)&X[(size_t)(m0 + r) * D_ + k0 + lc * 4];
                split4(xv, hi, lo);
                *(uint64_t*)((char*)sAh + r * 80 + lc * 8) = hi;
                *(uint64_t*)((char*)sAl + r * 80 + lc * 8) = lo;
            }
        } else {
#pragma unroll
            for (int i = 0; i < 2; i++) {
                const int idx = tid + i * 256;
                const int rr = idx >> 2;
                const int cc = idx & 3;
                const size_t g = (size_t)(m0 + rr) * D_ + k0 + cc * 8;
                *(uint4*)((char*)sAh + rr * 80 + cc * 16) = *(const uint4*)&Ah[g];
                *(uint4*)((char*)sAl + rr * 80 + cc * 16) = *(const uint4*)&Al[g];
            }
        }
#pragma unroll
        for (int it = 0; it < 4; it++) {
            const int r = lr + it * 32;
            uint64_t hi, lo;
            float4 wv = *(const float4*)&W[(size_t)(n0 + r) * D_ + k0 + lc * 4];
            split4(wv, hi, lo);
            *(uint64_t*)((char*)sBh + r * 80 + lc * 8) = hi;
            *(uint64_t*)((char*)sBl + r * 80 + lc * 8) = lo;
        }
        __syncthreads();

#pragma unroll
        for (int ks = 0; ks < 2; ks++) {
            const uint32_t kbyte = (uint32_t)(ks * 32);
            uint32_t bh[2][4], bl[2][4];
#pragma unroll
            for (int p = 0; p < 2; p++) {
                ldsm4(bh[p], bBh + (uint32_t)((wn * 32 + p * 16) * 80) + kbyte + boff);
                ldsm4(bl[p], bBl + (uint32_t)((wn * 32 + p * 16) * 80) + kbyte + boff);
            }
            {
                uint32_t a[4][4];
#pragma unroll
                for (int i = 0; i < 4; i++)
                    ldsm4(a[i], bAh + (uint32_t)((wm * 64 + i * 16) * 80) + kbyte + aoff);
#pragma unroll
                for (int i = 0; i < 4; i++)
#pragma unroll
                    for (int j = 0; j < 4; j++) {
                        mma16816(C[i][j], a[i][0], a[i][1], a[i][2], a[i][3],
                                 bh[j >> 1][(j & 1) * 2], bh[j >> 1][(j & 1) * 2 + 1]);
                        mma16816(C[i][j], a[i][0], a[i][1], a[i][2], a[i][3],
                                 bl[j >> 1][(j & 1) * 2], bl[j >> 1][(j & 1) * 2 + 1]);
                    }
            }
            {
                uint32_t a[4][4];
#pragma unroll
                for (int i = 0; i < 4; i++)
                    ldsm4(a[i], bAl + (uint32_t)((wm * 64 + i * 16) * 80) + kbyte + aoff);
#pragma unroll
                for (int i = 0; i < 4; i++)
#pragma unroll
                    for (int j = 0; j < 4; j++)
                        mma16816(C[i][j], a[i][0], a[i][1], a[i][2], a[i][3],
                                 bh[j >> 1][(j & 1) * 2], bh[j >> 1][(j & 1) * 2 + 1]);
            }
        }
    }

    const int qr = lane >> 2;
    const int qc = (lane & 3) * 2;
#pragma unroll
    for (int i = 0; i < 4; i++) {
        const int row0 = m0 + wm * 64 + i * 16 + qr;
#pragma unroll
        for (int j = 0; j < 4; j++) {
            const int col = n0 + wn * 32 + j * 8 + qc;
            const float b0v = bias[col], b1v = bias[col + 1];
            float v0 = C[i][j][0] + b0v, v1 = C[i][j][1] + b1v;
            float v2 = C[i][j][2] + b0v, v3 = C[i][j][3] + b1v;
            if (MODE == 0) {
                __nv_bfloat16 h0 = __float2bfloat16_rn(v0);
                __nv_bfloat16 h1 = __float2bfloat16_rn(v1);
                __nv_bfloat16 h2 = __float2bfloat16_rn(v2);
                __nv_bfloat16 h3 = __float2bfloat16_rn(v3);
                __nv_bfloat162 hp0; hp0.x = h0; hp0.y = h1;
                __nv_bfloat162 hp1; hp1.x = h2; hp1.y = h3;
                *(uint32_t*)&Yh[(size_t)row0 * D_ + col]       = *(uint32_t*)&hp0;
                *(uint32_t*)&Yh[(size_t)(row0 + 8) * D_ + col] = *(uint32_t*)&hp1;
                *(uint32_t*)&Yl[(size_t)row0 * D_ + col] =
                    packbf(v0 - __bfloat162float(h0), v1 - __bfloat162float(h1));
                *(uint32_t*)&Yl[(size_t)(row0 + 8) * D_ + col] =
                    packbf(v2 - __bfloat162float(h2), v3 - __bfloat162float(h3));
            } else {
                float2 o0 = { v0, v1 };
                float2 o1 = { v2, v3 };
                *(float2*)&Yf[(size_t)row0 * D_ + col]       = o0;
                *(float2*)&Yf[(size_t)(row0 + 8) * D_ + col] = o1;
            }
        }
    }
}

// ===========================================================================
// Flash attention — R6's best-measured body (341us): plain uint4 loads,
// 73KB smem, interleaved MMA order. Only change: pre-split Ch/Cl epilogue.
// ===========================================================================
#define ATQ 128
#define ATK 64
#define ALD 144

#define AOFF_QH 0
#define AOFF_QL (AOFF_QH + ATQ * ALD)
#define AOFF_KH (AOFF_QL + ATQ * ALD)
#define AOFF_KL (AOFF_KH + ATK * ALD)
#define AOFF_VH (AOFF_KL + ATK * ALD)
#define AOFF_VL (AOFF_VH + ATK * ALD)
#define ATTN_SMEM_BYTES (AOFF_VL + ATK * ALD)  // 73728

__global__ __launch_bounds__(256) void attn_mma_kernel(
    const __nv_bfloat16* __restrict__ Qh, const __nv_bfloat16* __restrict__ Ql,
    const __nv_bfloat16* __restrict__ Kh, const __nv_bfloat16* __restrict__ Kl,
    const __nv_bfloat16* __restrict__ Vh, const __nv_bfloat16* __restrict__ Vl,
    const int* __restrict__ mask,
    __nv_bfloat16* __restrict__ Ch, __nv_bfloat16* __restrict__ Cl)
{
    extern __shared__ __align__(128) char smem[];
    const uint32_t sb = smem_u32(smem);

    const int tid  = threadIdx.x;
    const int lane = tid & 31;
    const int wid  = tid >> 5;
    const int bh = blockIdx.y;
    const int b  = bh >> 4;
    const int h  = bh & 15;
    const int q0 = blockIdx.x * ATQ;

    const size_t base = (size_t)b * S_ * D_ + (size_t)h * DK_;
    const __nv_bfloat16* Qhb = Qh + base;
    const __nv_bfloat16* Qlb = Ql + base;
    const __nv_bfloat16* Khb = Kh + base;
    const __nv_bfloat16* Klb = Kl + base;
    const __nv_bfloat16* Vhb = Vh + base;
    const __nv_bfloat16* Vlb = Vl + base;
    const int* Mb = mask + (size_t)b * S_ * S_;

    // ---- load Q tile (128 x 64 bf16 hi/lo): uint4 copies ----
#pragma unroll
    for (int i = 0; i < 4; i++) {
        const int idx = tid + i * 256;
        const int rr = idx >> 3;
        const int cc = idx & 7;
        *(uint4*)(smem + AOFF_QH + rr * ALD + cc * 16) =
            *(const uint4*)&Qhb[(size_t)(q0 + rr) * D_ + cc * 8];
        *(uint4*)(smem + AOFF_QL + rr * ALD + cc * 16) =
            *(const uint4*)&Qlb[(size_t)(q0 + rr) * D_ + cc * 8];
    }

    const uint32_t aoffQ = sb + (uint32_t)((wid * 16 + (lane & 15)) * ALD + (lane >> 4) * 16);
    const uint32_t boffK = sb + (uint32_t)(((lane & 7) + ((lane >> 4) & 1) * 8) * ALD +
                                           ((lane >> 3) & 1) * 16);
    const uint32_t voffV = sb + (uint32_t)((((lane >> 3) & 1) * 8 + (lane & 7)) * ALD +
                                           ((lane >> 4) & 1) * 16);

    float mstate[2] = { -1e30f, -1e30f };
    float lstate[2] = { 0.0f, 0.0f };
    float O[8][4];
#pragma unroll
    for (int j = 0; j < 8; j++)
#pragma unroll
        for (int t = 0; t < 4; t++) O[j][t] = 0.0f;

    const int row0 = q0 + wid * 16 + (lane >> 2);
    const int mcol = (lane & 3) * 2;
    const int* mrow0 = Mb + (size_t)row0 * S_;
    const int* mrow1 = Mb + (size_t)(row0 + 8) * S_;

    for (int k0 = 0; k0 < S_; k0 += ATK) {
        __syncthreads();
        // ---- load K,V tiles (64 x 64 bf16 hi/lo): uint4 copies ----
#pragma unroll
        for (int i = 0; i < 2; i++) {
            const int idx = tid + i * 256;
            const int rr = idx >> 3;
            const int cc = idx & 7;
            const size_t g = (size_t)(k0 + rr) * D_ + cc * 8;
            *(uint4*)(smem + AOFF_KH + rr * ALD + cc * 16) = *(const uint4*)&Khb[g];
            *(uint4*)(smem + AOFF_KL + rr * ALD + cc * 16) = *(const uint4*)&Klb[g];
            *(uint4*)(smem + AOFF_VH + rr * ALD + cc * 16) = *(const uint4*)&Vhb[g];
            *(uint4*)(smem + AOFF_VL + rr * ALD + cc * 16) = *(const uint4*)&Vlb[g];
        }
        __syncthreads();

        // ---- S = Q K^T (split compensated) ----
        float Sf[8][4];
#pragma unroll
        for (int j = 0; j < 8; j++)
#pragma unroll
            for (int tt = 0; tt < 4; tt++) Sf[j][tt] = 0.0f;

#pragma unroll
        for (int kc = 0; kc < 4; kc++) {
            const uint32_t kb = (uint32_t)(kc * 32);
            uint32_t ah[4], al[4];
            ldsm4(ah, aoffQ + AOFF_QH + kb);
            ldsm4(al, aoffQ + AOFF_QL + kb);
#pragma unroll
            for (int jp = 0; jp < 4; jp++) {
                uint32_t kh[4], kl[4];
                ldsm4(kh, boffK + AOFF_KH + (uint32_t)(jp * 16 * ALD) + kb);
                ldsm4(kl, boffK + AOFF_KL + (uint32_t)(jp * 16 * ALD) + kb);
                mma16816(Sf[jp * 2],     ah[0], ah[1], ah[2], ah[3], kh[0], kh[1]);
                mma16816(Sf[jp * 2],     ah[0], ah[1], ah[2], ah[3], kl[0], kl[1]);
                mma16816(Sf[jp * 2],     al[0], al[1], al[2], al[3], kh[0], kh[1]);
                mma16816(Sf[jp * 2 + 1], ah[0], ah[1], ah[2], ah[3], kh[2], kh[3]);
                mma16816(Sf[jp * 2 + 1], ah[0], ah[1], ah[2], ah[3], kl[2], kl[3]);
                mma16816(Sf[jp * 2 + 1], al[0], al[1], al[2], al[3], kh[2], kh[3]);
            }
        }

        // ---- scale + mask ----
#pragma unroll
        for (int j = 0; j < 8; j++) {
            int2 mv0 = *(const int2*)&mrow0[k0 + j * 8 + mcol];
            int2 mv1 = *(const int2*)&mrow1[k0 + j * 8 + mcol];
            Sf[j][0] = (mv0.x == 0) ? -1e9f : Sf[j][0] * 0.125f;
            Sf[j][1] = (mv0.y == 0) ? -1e9f : Sf[j][1] * 0.125f;
            Sf[j][2] = (mv1.x == 0) ? -1e9f : Sf[j][2] * 0.125f;
            Sf[j][3] = (mv1.y == 0) ? -1e9f : Sf[j][3] * 0.125f;
        }

        // ---- online softmax ----
        float corr[2];
#pragma unroll
        for (int rr = 0; rr < 2; rr++) {
            float mx = -1e30f;
#pragma unroll
            for (int j = 0; j < 8; j++)
                mx = fmaxf(mx, fmaxf(Sf[j][rr * 2], Sf[j][rr * 2 + 1]));
            mx = fmaxf(mx, __shfl_xor_sync(0xFFFFFFFF, mx, 1));
            mx = fmaxf(mx, __shfl_xor_sync(0xFFFFFFFF, mx, 2));
            float mnew = fmaxf(mstate[rr], mx);
            corr[rr] = __expf(mstate[rr] - mnew);
            float sum = 0.0f;
#pragma unroll
            for (int j = 0; j < 8; j++) {
                float p0 = __expf(Sf[j][rr * 2]     - mnew);
                float p1 = __expf(Sf[j][rr * 2 + 1] - mnew);
                Sf[j][rr * 2] = p0; Sf[j][rr * 2 + 1] = p1;
                sum += p0 + p1;
            }
            sum += __shfl_xor_sync(0xFFFFFFFF, sum, 1);
            sum += __shfl_xor_sync(0xFFFFFFFF, sum, 2);
            lstate[rr] = lstate[rr] * corr[rr] + sum;
            mstate[rr] = mnew;
        }

#pragma unroll
        for (int j = 0; j < 8; j++) {
            O[j][0] *= corr[0]; O[j][1] *= corr[0];
            O[j][2] *= corr[1]; O[j][3] *= corr[1];
        }

        // ---- pack P (hi/lo split) ----
        uint32_t aPh[4][4], aPl[4][4];
#pragma unroll
        for (int kc = 0; kc < 4; kc++) {
#pragma unroll
            for (int half = 0; half < 2; half++) {
                const int j = kc * 2 + half;
#pragma unroll
                for (int rr = 0; rr < 2; rr++) {
                    float p0 = Sf[j][rr * 2], p1 = Sf[j][rr * 2 + 1];
                    __nv_bfloat16 h0 = __float2bfloat16_rn(p0);
                    __nv_bfloat16 h1 = __float2bfloat16_rn(p1);
                    __nv_bfloat162 hp; hp.x = h0; hp.y = h1;
                    aPh[kc][half * 2 + rr] = *(uint32_t*)&hp;
                    aPl[kc][half * 2 + rr] =
                        packbf(p0 - __bfloat162float(h0), p1 - __bfloat162float(h1));
                }
            }
        }

        // ---- O += P V (split compensated) ----
#pragma unroll
        for (int kc = 0; kc < 4; kc++) {
#pragma unroll
            for (int jp = 0; jp < 4; jp++) {
                uint32_t vh[4], vl[4];
                ldsm4t(vh, voffV + AOFF_VH + (uint32_t)(kc * 16 * ALD) + (uint32_t)(jp * 32));
                ldsm4t(vl, voffV + AOFF_VL + (uint32_t)(kc * 16 * ALD) + (uint32_t)(jp * 32));
                mma16816(O[jp * 2],     aPh[kc][0], aPh[kc][1], aPh[kc][2], aPh[kc][3], vh[0], vh[1]);
                mma16816(O[jp * 2],     aPh[kc][0], aPh[kc][1], aPh[kc][2], aPh[kc][3], vl[0], vl[1]);
                mma16816(O[jp * 2],     aPl[kc][0], aPl[kc][1], aPl[kc][2], aPl[kc][3], vh[0], vh[1]);
                mma16816(O[jp * 2 + 1], aPh[kc][0], aPh[kc][1], aPh[kc][2], aPh[kc][3], vh[2], vh[3]);
                mma16816(O[jp * 2 + 1], aPh[kc][0], aPh[kc][1], aPh[kc][2], aPh[kc][3], vl[2], vl[3]);
                mma16816(O[jp * 2 + 1], aPl[kc][0], aPl[kc][1], aPl[kc][2], aPl[kc][3], vh[2], vh[3]);
            }
        }
        __syncthreads();
    }

    // ---- finalize: write pre-split context ----
    const float inv0 = 1.0f / lstate[0];
    const float inv1 = 1.0f / lstate[1];
    __nv_bfloat16* Chb = Ch + base;
    __nv_bfloat16* Clb = Cl + base;
#pragma unroll
    for (int j = 0; j < 8; j++) {
        const int col = j * 8 + mcol;
        float v0 = O[j][0] * inv0, v1 = O[j][1] * inv0;
        float v2 = O[j][2] * inv1, v3 = O[j][3] * inv1;
        __nv_bfloat16 h0 = __float2bfloat16_rn(v0);
        __nv_bfloat16 h1 = __float2bfloat16_rn(v1);
        __nv_bfloat16 h2 = __float2bfloat16_rn(v2);
        __nv_bfloat16 h3 = __float2bfloat16_rn(v3);
        __nv_bfloat162 hp0; hp0.x = h0; hp0.y = h1;
        __nv_bfloat162 hp1; hp1.x = h2; hp1.y = h3;
        *(uint32_t*)&Chb[(size_t)row0 * D_ + col]       = *(uint32_t*)&hp0;
        *(uint32_t*)&Chb[(size_t)(row0 + 8) * D_ + col] = *(uint32_t*)&hp1;
        *(uint32_t*)&Clb[(size_t)row0 * D_ + col] =
            packbf(v0 - __bfloat162float(h0), v1 - __bfloat162float(h1));
        *(uint32_t*)&Clb[(size_t)(row0 + 8) * D_ + col] =
            packbf(v2 - __bfloat162float(h2), v3 - __bfloat162float(h3));
    }
}

// ---------------------------------------------------------------------------
// Launch
// ---------------------------------------------------------------------------
extern "C" void kernel_launch(void* const* d_in, const int* in_sizes, int n_in,
                              void* d_out, int out_size)
{
    (void)in_sizes; (void)n_in; (void)out_size;
    const float* q    = (const float*)d_in[0];
    const float* k    = (const float*)d_in[1];
    const float* v    = (const float*)d_in[2];
    const int*   mask = (const int*)d_in[3];
    const float* w_q  = (const float*)d_in[4];
    const float* b_q  = (const float*)d_in[5];
    const float* w_k  = (const float*)d_in[6];
    const float* b_k  = (const float*)d_in[7];
    const float* w_v  = (const float*)d_in[8];
    const float* b_v  = (const float*)d_in[9];
    const float* w_o  = (const float*)d_in[10];
    const float* b_o  = (const float*)d_in[11];
    float* out = (float*)d_out;

    __nv_bfloat16 *gQh, *gQl, *gKh, *gKl, *gVh, *gVl, *gCh, *gCl;
    cudaGetSymbolAddress((void**)&gQh, g_Qh);
    cudaGetSymbolAddress((void**)&gQl, g_Ql);
    cudaGetSymbolAddress((void**)&gKh, g_Kh);
    cudaGetSymbolAddress((void**)&gKl, g_Kl);
    cudaGetSymbolAddress((void**)&gVh, g_Vh);
    cudaGetSymbolAddress((void**)&gVl, g_Vl);
    cudaGetSymbolAddress((void**)&gCh, g_Ch);
    cudaGetSymbolAddress((void**)&gCl, g_Cl);

    cudaFuncSetAttribute(attn_mma_kernel,
                         cudaFuncAttributeMaxDynamicSharedMemorySize,
                         ATTN_SMEM_BYTES);

    dim3 gblk(256);

    // Q/K/V projections batched over z (R7 version, 251us)
    dim3 ggrid3(D_ / BN, M_ / BM, 3);
    gemm_mma_kernel<0><<<ggrid3, gblk>>>(
        q, k, v, nullptr, nullptr,
        w_q, w_k, w_v, b_q, b_k, b_v,
        nullptr,
        gQh, gKh, gVh, gQl, gKl, gVl);

    dim3 ablk(256);
    dim3 agrid(S_ / ATQ, B_ * H_);    // (16, 32)
    attn_mma_kernel<<<agrid, ablk, ATTN_SMEM_BYTES>>>(
        gQh, gQl, gKh, gKl, gVh, gVl, mask, gCh, gCl);

    // final projection (pre-split A)
    dim3 ggrid1(D_ / BN, M_ / BM, 1);
    gemm_mma_kernel<1><<<ggrid1, gblk>>>(
        nullptr, nullptr, nullptr, gCh, gCl,
        w_o, nullptr, nullptr, b_o, nullptr, nullptr,
        out,
        nullptr, nullptr, nullptr, nullptr, nullptr, nullptr);
}